// round 1
// baseline (speedup 1.0000x reference)
#include <cuda_runtime.h>
#include <cuda_bf16.h>

// 8x8 DCT-II coefficients, 0.5*cos(pi*(2m+1)k/16) pre-folded.
#define K0 0.3535533905932738f   // 1/(2*sqrt(2))  (also 0.5*c4)
#define K1 0.4903926402016152f   // 0.5*cos(pi/16)
#define K2 0.4619397662556434f   // 0.5*cos(2pi/16)
#define K3 0.4157348061512726f   // 0.5*cos(3pi/16)
#define K5 0.2777851165098011f   // 0.5*cos(5pi/16)
#define K6 0.1913417161825449f   // 0.5*cos(6pi/16)
#define K7 0.0975451610080642f   // 0.5*cos(7pi/16)

// In-place 8-point DCT-II (orthonormal), butterfly (even/odd) form.
__device__ __forceinline__ void dct8(float* v) {
    float s0 = v[0] + v[7], s1 = v[1] + v[6], s2 = v[2] + v[5], s3 = v[3] + v[4];
    float d0 = v[0] - v[7], d1 = v[1] - v[6], d2 = v[2] - v[5], d3 = v[3] - v[4];
    float e0 = s0 + s3, e1 = s1 + s2;
    float o0 = s0 - s3, o1 = s1 - s2;
    v[0] = K0 * (e0 + e1);
    v[4] = K0 * (e0 - e1);
    v[2] = K2 * o0 + K6 * o1;
    v[6] = K6 * o0 - K2 * o1;
    v[1] = K1 * d0 + K3 * d1 + K5 * d2 + K7 * d3;
    v[3] = K3 * d0 - K7 * d1 - K1 * d2 - K5 * d3;
    v[5] = K5 * d0 - K1 * d1 + K7 * d2 + K3 * d3;
    v[7] = K7 * d0 - K5 * d1 + K3 * d2 - K1 * d3;
}

__global__ void __launch_bounds__(256)
dct_quant_kernel(const float* __restrict__ x,
                 const float* __restrict__ q,
                 float* __restrict__ out,
                 int nblocks) {
    __shared__ float srq[64];
    if (threadIdx.x < 64) srq[threadIdx.x] = 1.0f / q[threadIdx.x];
    __syncthreads();

    int g = blockIdx.x * 256 + threadIdx.x;
    if (g >= nblocks) return;

    // image layout: each (n,c) is a 128x128 plane = 16x16 blocks of 8x8
    int img = g >> 8;
    int rem = g & 255;
    int br  = rem >> 4;
    int bc  = rem & 15;
    long off = ((long)img << 14) + (br << 10) + (bc << 3);
    const float* base = x + off;

    float X[64];
    // Front-batched vectorized loads: 16x LDG.128
    #pragma unroll
    for (int j = 0; j < 8; j++) {
        float4 a = *reinterpret_cast<const float4*>(base + j * 128);
        float4 b = *reinterpret_cast<const float4*>(base + j * 128 + 4);
        X[j * 8 + 0] = a.x; X[j * 8 + 1] = a.y; X[j * 8 + 2] = a.z; X[j * 8 + 3] = a.w;
        X[j * 8 + 4] = b.x; X[j * 8 + 5] = b.y; X[j * 8 + 6] = b.z; X[j * 8 + 7] = b.w;
    }

    // Row pass
    #pragma unroll
    for (int j = 0; j < 8; j++) dct8(&X[j * 8]);

    // Column pass + quantize/round/clip
    #pragma unroll
    for (int k = 0; k < 8; k++) {
        float t[8];
        #pragma unroll
        for (int i = 0; i < 8; i++) t[i] = X[i * 8 + k];
        dct8(t);
        #pragma unroll
        for (int i = 0; i < 8; i++) {
            float y = rintf(t[i] * srq[i * 8 + k]);   // round half-to-even, like jnp.round
            y = fminf(fmaxf(y, -128.0f), 127.0f);
            X[i * 8 + k] = y;
        }
    }

    float* obase = out + off;
    #pragma unroll
    for (int j = 0; j < 8; j++) {
        float4 a, b;
        a.x = X[j * 8 + 0]; a.y = X[j * 8 + 1]; a.z = X[j * 8 + 2]; a.w = X[j * 8 + 3];
        b.x = X[j * 8 + 4]; b.y = X[j * 8 + 5]; b.z = X[j * 8 + 6]; b.w = X[j * 8 + 7];
        *reinterpret_cast<float4*>(obase + j * 128)     = a;
        *reinterpret_cast<float4*>(obase + j * 128 + 4) = b;
    }
}

extern "C" void kernel_launch(void* const* d_in, const int* in_sizes, int n_in,
                              void* d_out, int out_size) {
    const float* x = (const float*)d_in[0];
    const float* q = (const float*)d_in[1];
    float* out = (float*)d_out;

    int nelem = in_sizes[0];           // 32*64*128*128 = 33554432
    int nblocks = nelem / 64;          // 524288 8x8 blocks
    int grid = (nblocks + 255) / 256;  // 2048 CTAs

    dct_quant_kernel<<<grid, 256>>>(x, q, out, nblocks);
}

// round 3
// speedup vs baseline: 1.0839x; 1.0839x over previous
#include <cuda_runtime.h>
#include <cuda_bf16.h>

// 8x8 DCT-II coefficients, 0.5*cos(pi*(2m+1)k/16) pre-folded (orthonormal).
#define K0 0.3535533905932738f   // 1/(2*sqrt(2))
#define K1 0.4903926402016152f
#define K2 0.4619397662556434f
#define K3 0.4157348061512726f
#define K5 0.2777851165098011f
#define K6 0.1913417161825449f
#define K7 0.0975451610080642f

// In-place 8-point DCT-II (orthonormal), butterfly (even/odd) form.
__device__ __forceinline__ void dct8(float* v) {
    float s0 = v[0] + v[7], s1 = v[1] + v[6], s2 = v[2] + v[5], s3 = v[3] + v[4];
    float d0 = v[0] - v[7], d1 = v[1] - v[6], d2 = v[2] - v[5], d3 = v[3] - v[4];
    float e0 = s0 + s3, e1 = s1 + s2;
    float o0 = s0 - s3, o1 = s1 - s2;
    v[0] = K0 * (e0 + e1);
    v[4] = K0 * (e0 - e1);
    v[2] = K2 * o0 + K6 * o1;
    v[6] = K6 * o0 - K2 * o1;
    v[1] = K1 * d0 + K3 * d1 + K5 * d2 + K7 * d3;
    v[3] = K3 * d0 - K7 * d1 - K1 * d2 - K5 * d3;
    v[5] = K5 * d0 - K1 * d1 + K7 * d2 + K3 * d3;
    v[7] = K7 * d0 - K5 * d1 + K3 * d2 - K1 * d3;
}

// Warp = 4 horizontally adjacent 8x8 blocks (an 8x32 tile, rows = 128B).
// Thread (j = lane>>2, b = lane&3): row j of block b.
__global__ void __launch_bounds__(256)
dct_quant_kernel(const float* __restrict__ x,
                 const float* __restrict__ q,
                 float* __restrict__ out,
                 int nwarps) {
    __shared__ float srq[64];
    if (threadIdx.x < 64) srq[threadIdx.x] = 1.0f / q[threadIdx.x];
    __syncthreads();

    int w = blockIdx.x * 8 + (threadIdx.x >> 5);
    if (w >= nwarps) return;
    int lane = threadIdx.x & 31;
    int j = lane >> 2;   // row within block; becomes horizontal-freq index after transpose
    int b = lane & 3;    // block within tile

    // tiles: 2048 planes x 16 block-rows x 4 tile-cols
    int img = w >> 6;
    int br  = (w >> 2) & 15;
    int tc  = w & 3;
    long tile = ((long)img << 14) + (br << 10) + (tc << 5);

    const float* base = x + tile + j * 128 + b * 8;
    float4 lo = *reinterpret_cast<const float4*>(base);
    float4 hi = *reinterpret_cast<const float4*>(base + 4);

    float r[8];
    r[0] = lo.x; r[1] = lo.y; r[2] = lo.z; r[3] = lo.w;
    r[4] = hi.x; r[5] = hi.y; r[6] = hi.z; r[7] = hi.w;

    // Row pass (along memory-contiguous dimension)
    dct8(r);

    // 8x8 transpose across the 8 threads of this block (lane stride 4):
    // 3 butterfly stages, each exchanging j-bit s with register-index bit s.
    #pragma unroll
    for (int s = 0; s < 3; s++) {
        const int m = 1 << s;
        int bit = (j & m);
        #pragma unroll
        for (int i = 0; i < 8; i++) {
            if ((i & m) == 0) {
                float send = bit ? r[i] : r[i | m];
                float recv = __shfl_xor_sync(0xffffffffu, send, m << 2);
                if (bit) r[i] = recv; else r[i | m] = recv;
            }
        }
    }

    // Column pass: register index v = vertical frequency, thread j = horizontal frequency
    dct8(r);

    // Quantize + round-half-even + clip, store column-oriented.
    // For fixed v, the warp writes tile + v*128 + {b*8+j over lanes} = one
    // contiguous, fully-coalesced 128B segment per STG.32.
    float* obase = out + tile + b * 8 + j;
    #pragma unroll
    for (int v = 0; v < 8; v++) {
        float y = rintf(r[v] * srq[v * 8 + j]);
        y = fminf(fmaxf(y, -128.0f), 127.0f);
        obase[v * 128] = y;
    }
}

extern "C" void kernel_launch(void* const* d_in, const int* in_sizes, int n_in,
                              void* d_out, int out_size) {
    const float* x = (const float*)d_in[0];
    const float* q = (const float*)d_in[1];
    float* out = (float*)d_out;

    int nelem  = in_sizes[0];         // 33554432
    int nwarps = nelem / 256;         // 131072 warps (4 blocks each)
    int grid   = (nwarps + 7) / 8;    // 16384 CTAs of 256 threads

    dct_quant_kernel<<<grid, 256>>>(x, q, out, nwarps);
}

// round 4
// speedup vs baseline: 1.0900x; 1.0056x over previous
#include <cuda_runtime.h>
#include <cuda_bf16.h>

// 8x8 DCT-II coefficients, 0.5*cos(pi*(2m+1)k/16) pre-folded (orthonormal).
#define K0 0.3535533905932738f   // 1/(2*sqrt(2))
#define K1 0.4903926402016152f
#define K2 0.4619397662556434f
#define K3 0.4157348061512726f
#define K5 0.2777851165098011f
#define K6 0.1913417161825449f
#define K7 0.0975451610080642f

// In-place 8-point DCT-II (orthonormal), butterfly (even/odd) form.
__device__ __forceinline__ void dct8(float* v) {
    float s0 = v[0] + v[7], s1 = v[1] + v[6], s2 = v[2] + v[5], s3 = v[3] + v[4];
    float d0 = v[0] - v[7], d1 = v[1] - v[6], d2 = v[2] - v[5], d3 = v[3] - v[4];
    float e0 = s0 + s3, e1 = s1 + s2;
    float o0 = s0 - s3, o1 = s1 - s2;
    v[0] = K0 * (e0 + e1);
    v[4] = K0 * (e0 - e1);
    v[2] = K2 * o0 + K6 * o1;
    v[6] = K6 * o0 - K2 * o1;
    v[1] = K1 * d0 + K3 * d1 + K5 * d2 + K7 * d3;
    v[3] = K3 * d0 - K7 * d1 - K1 * d2 - K5 * d3;
    v[5] = K5 * d0 - K1 * d1 + K7 * d2 + K3 * d3;
    v[7] = K7 * d0 - K5 * d1 + K3 * d2 - K1 * d3;
}

// Warp = 4 horizontally adjacent 8x8 blocks (an 8x32 tile, rows = 128B).
// Thread (j = lane>>2, b = lane&3): row j of block b.
// Transpose through padded per-warp SMEM (bank-conflict-free both directions).
__global__ void __launch_bounds__(256)
dct_quant_kernel(const float* __restrict__ x,
                 const float* __restrict__ q,
                 float* __restrict__ out,
                 int nwarps) {
    __shared__ float srq[64];
    __shared__ float tr[8][4][8][9];   // [warp][block][col][row], pad 9

    if (threadIdx.x < 64) srq[threadIdx.x] = 1.0f / q[threadIdx.x];
    __syncthreads();

    int wid  = threadIdx.x >> 5;
    int w    = blockIdx.x * 8 + wid;
    if (w >= nwarps) return;
    int lane = threadIdx.x & 31;
    int j = lane >> 2;   // row within block (becomes horizontal-freq / column index)
    int b = lane & 3;    // block within tile

    // tiles: 2048 planes x 16 block-rows x 4 tile-cols
    int img = w >> 6;
    int br  = (w >> 2) & 15;
    int tc  = w & 3;
    long tile = ((long)img << 14) + (br << 10) + (tc << 5);

    const float* base = x + tile + j * 128 + b * 8;
    float4 lo = *reinterpret_cast<const float4*>(base);
    float4 hi = *reinterpret_cast<const float4*>(base + 4);

    float r[8];
    r[0] = lo.x; r[1] = lo.y; r[2] = lo.z; r[3] = lo.w;
    r[4] = hi.x; r[5] = hi.y; r[6] = hi.z; r[7] = hi.w;

    // Row pass (along memory-contiguous dimension)
    dct8(r);

    // Transposed write: tr[wid][b][c][j] = r[c].
    // Banks (8b + 9c + j) mod 32: all 32 distinct for fixed c -> conflict-free.
    float* ts = &tr[wid][b][0][0];
    #pragma unroll
    for (int c = 0; c < 8; c++) ts[c * 9 + j] = r[c];

    __syncwarp();

    // Row-contiguous read of the transposed data: r[i] = R[i][j] (column j).
    // Banks (8b + 9j + i) mod 32: all 32 distinct for fixed i -> conflict-free.
    #pragma unroll
    for (int i = 0; i < 8; i++) r[i] = ts[j * 9 + i];

    // Column pass: register index v = vertical frequency, j = horizontal frequency
    dct8(r);

    // Quantize + round-half-even + clip, store column-oriented.
    // For fixed v, warp writes tile + v*128 + {b*8+j over lanes}: one
    // contiguous, fully-coalesced 128B segment per STG.32.
    float* obase = out + tile + b * 8 + j;
    #pragma unroll
    for (int v = 0; v < 8; v++) {
        float y = rintf(r[v] * srq[v * 8 + j]);
        y = fminf(fmaxf(y, -128.0f), 127.0f);
        obase[v * 128] = y;
    }
}

extern "C" void kernel_launch(void* const* d_in, const int* in_sizes, int n_in,
                              void* d_out, int out_size) {
    const float* x = (const float*)d_in[0];
    const float* q = (const float*)d_in[1];
    float* out = (float*)d_out;

    int nelem  = in_sizes[0];         // 33554432
    int nwarps = nelem / 256;         // 131072 warps (4 blocks each)
    int grid   = (nwarps + 7) / 8;    // 16384 CTAs of 256 threads

    dct_quant_kernel<<<grid, 256>>>(x, q, out, nwarps);
}